// round 15
// baseline (speedup 1.0000x reference)
#include <cuda_runtime.h>
#include <math_constants.h>
#include <cstdint>

#define LEXP 64
#define KSEL 8
#define TMTOK 64         // tokens per CTA -> grid 256, 2-3 CTAs/SM resident
#define KC   32          // K floats per chunk (16 bf16x2 words per row)
#define NTHREADS 128
#define MAXCTAS 512
#define RSTR 20          // uint32 words per staged row -> conflict-free ldmatrix

#define XCOMP_W (TMTOK * RSTR)           // 1280 words per x component
#define WCOMP_W (LEXP * RSTR)            // 1280 words per w component
#define XTOT_W  (3 * XCOMP_W)            // 3840
#define WBUF_W  (3 * WCOMP_W)            // 3840 (one W buffer)
#define DYN_BYTES ((XTOT_W + 2 * WBUF_W) * 4)   // 46080 < 48KB default
#define SLW 66                            // slog row stride; 64*66*4=16896 fits

__device__ uint32_t g_wsplit[3][LEXP][1024];   // bf16x2 words, H=2048 -> 1024/row
__device__ int g_hist_cta[MAXCTAS][LEXP];
__device__ int g_act_cta[MAXCTAS];
__device__ int g_ticket;                       // zero-init; reset by last CTA

static __device__ __forceinline__ uint32_t cvt2(float hi, float lo) {
    uint32_t d;
    asm("cvt.rn.bf16x2.f32 %0, %1, %2;" : "=r"(d) : "f"(hi), "f"(lo));
    return d;
}
static __device__ __forceinline__ float lo_f(uint32_t p) { return __uint_as_float(p << 16); }
static __device__ __forceinline__ float hi_f(uint32_t p) { return __uint_as_float(p & 0xFFFF0000u); }

static __device__ __forceinline__ void split3(float f0, float f1,
                                              uint32_t& pa, uint32_t& pb, uint32_t& pc) {
    pa = cvt2(f1, f0);
    const float r0 = f0 - lo_f(pa), r1 = f1 - hi_f(pa);   // exact
    pb = cvt2(r1, r0);
    const float s0 = r0 - lo_f(pb), s1 = r1 - hi_f(pb);   // exact
    pc = cvt2(s1, s0);
}

static __device__ __forceinline__ void mma_bf16(float* d, const uint32_t* a,
                                                uint32_t b0, uint32_t b1) {
    asm volatile(
        "mma.sync.aligned.m16n8k16.row.col.f32.bf16.bf16.f32 "
        "{%0,%1,%2,%3}, {%4,%5,%6,%7}, {%8,%9}, {%0,%1,%2,%3};"
        : "+f"(d[0]), "+f"(d[1]), "+f"(d[2]), "+f"(d[3])
        : "r"(a[0]), "r"(a[1]), "r"(a[2]), "r"(a[3]), "r"(b0), "r"(b1));
}

static __device__ __forceinline__ void ldsm4(uint32_t* r, const uint32_t* p) {
    const uint32_t a = (uint32_t)__cvta_generic_to_shared(p);
    asm volatile("ldmatrix.sync.aligned.m8n8.x4.shared.b16 {%0,%1,%2,%3}, [%4];"
        : "=r"(r[0]), "=r"(r[1]), "=r"(r[2]), "=r"(r[3]) : "r"(a));
}

static __device__ __forceinline__ void cpasync16(const uint32_t* dst_smem,
                                                 const uint32_t* src_gmem) {
    const uint32_t d = (uint32_t)__cvta_generic_to_shared(dst_smem);
    asm volatile("cp.async.cg.shared.global [%0], [%1], 16;"
                 :: "r"(d), "l"(src_gmem));
}

__global__ void wsplit_kernel(const float* __restrict__ Wr, int H) {
    const int e = blockIdx.x;           // 64 experts
    const int t = threadIdx.x;          // 256
    const int nw = H / 2;               // 1024 words
    for (int w = t; w < nw; w += 256) {
        const float f0 = Wr[(size_t)e * H + 2 * w];
        const float f1 = Wr[(size_t)e * H + 2 * w + 1];
        uint32_t a, b, c;
        split3(f0, f1, a, b, c);
        g_wsplit[0][e][w] = a;
        g_wsplit[1][e][w] = b;
        g_wsplit[2][e][w] = c;
    }
}

extern __shared__ __align__(16) uint32_t dyn_w[];

__global__ void __launch_bounds__(NTHREADS, 3)
router_kernel(const float* __restrict__ x, const float* __restrict__ Wr,
              const float* __restrict__ bias, const unsigned char* __restrict__ mask,
              float* __restrict__ out_sel, float* __restrict__ out_prob,
              float* __restrict__ out_scal, int has_vio, int M, int H)
{
    uint32_t* xw = dyn_w;                        // 3 x-components, comp*XCOMP_W
    uint32_t* wb0 = dyn_w + XTOT_W;              // W buffer 0
    uint32_t* wb1 = dyn_w + XTOT_W + WBUF_W;     // W buffer 1
    float* slog = (float*)dyn_w;                 // alias, post-drain

    __shared__ float sbias[LEXP];
    __shared__ int   shist[LEXP];
    __shared__ int   spart[2][LEXP];
    __shared__ int   sactive, smask32, sflag, sred;

    const int tid = threadIdx.x;
    const int wid = tid >> 5;
    const int lane = tid & 31;
    const int tokBase = blockIdx.x * TMTOK;
    const int ncta = gridDim.x;

    if (tid < LEXP) { sbias[tid] = bias[tid]; shist[tid] = 0; }
    if (tid == 0) {
        sactive = 0; sred = 0;
        const unsigned char mb0 = mask[0];
        const unsigned char mb1 = mask[1];
        smask32 = (mb0 != 0 && mb1 != 0) ? 0 : 1;
    }

    // all 4 warps MMA; warp owns one 16-token mtile over full K (R11 acc order)
    const int rowbase = wid * 16;
    const int fr = lane >> 2;
    const int fk = lane & 3;

    float acc[8][4];
#pragma unroll
    for (int n = 0; n < 8; ++n)
#pragma unroll
        for (int j = 0; j < 4; ++j) acc[n][j] = 0.f;

    // staging: 16 rows per pass (4 passes), 8 lanes x float4 per row
    const int srow = tid >> 3;          // 0..15
    const int sq = tid & 7;

    float4 xr[4];
    const int nchunk = H / KC;

    // ---- prologue: cp.async W chunk 0 -> wb0; prefetch x chunk 0 ----
#pragma unroll
    for (int i = 0; i < 6; ++i) {
        const int idx = i * NTHREADS + tid;       // 0..767
        const int rc = idx >> 2, q = idx & 3;     // rc = comp*64 + expert
        cpasync16(wb0 + (rc >> 6) * WCOMP_W + (rc & 63) * RSTR + q * 4,
                  &g_wsplit[rc >> 6][rc & 63][q * 4]);
    }
    asm volatile("cp.async.commit_group;");
#pragma unroll
    for (int p = 0; p < 4; ++p) {
        const int gtok = tokBase + p * 16 + srow;
        xr[p] = (gtok < M) ? *(const float4*)(x + (size_t)gtok * H + sq * 4)
                           : make_float4(0.f, 0.f, 0.f, 0.f);
    }

    for (int c = 0; c < nchunk; ++c) {
        __syncthreads();                // previous chunk's MMA reads complete
        // ---- convert + store x chunk c ----
#pragma unroll
        for (int p = 0; p < 4; ++p) {
            const int base = (p * 16 + srow) * RSTR + sq * 2;
            uint32_t a0, b0, c0, a1, b1, c1;
            split3(xr[p].x, xr[p].y, a0, b0, c0);
            split3(xr[p].z, xr[p].w, a1, b1, c1);
            *(unsigned long long*)&xw[base]               = (unsigned long long)a0 | ((unsigned long long)a1 << 32);
            *(unsigned long long*)&xw[XCOMP_W + base]     = (unsigned long long)b0 | ((unsigned long long)b1 << 32);
            *(unsigned long long*)&xw[2 * XCOMP_W + base] = (unsigned long long)c0 | ((unsigned long long)c1 << 32);
        }
        // ---- issue W chunk c+1 (cp.async) + prefetch x chunk c+1 ----
        if (c + 1 < nchunk) {
            uint32_t* wnext = ((c + 1) & 1) ? wb1 : wb0;
            const int kw = (c + 1) * (KC / 2);
#pragma unroll
            for (int i = 0; i < 6; ++i) {
                const int idx = i * NTHREADS + tid;
                const int rc = idx >> 2, q = idx & 3;
                cpasync16(wnext + (rc >> 6) * WCOMP_W + (rc & 63) * RSTR + q * 4,
                          &g_wsplit[rc >> 6][rc & 63][kw + q * 4]);
            }
            asm volatile("cp.async.commit_group;");
            const int kb = (c + 1) * KC;
#pragma unroll
            for (int p = 0; p < 4; ++p) {
                const int gtok = tokBase + p * 16 + srow;
                xr[p] = (gtok < M) ? *(const float4*)(x + (size_t)gtok * H + kb + sq * 4)
                                   : make_float4(0.f, 0.f, 0.f, 0.f);
            }
            asm volatile("cp.async.wait_group 1;");   // chunk c's W resident
        } else {
            asm volatile("cp.async.wait_group 0;");
        }
        __syncthreads();

        // ---- MMA: 2 ksteps x 8 ntiles x 6 products (R11 order, bit-exact) ----
        const uint32_t* wcur = (c & 1) ? wb1 : wb0;
#pragma unroll
        for (int s = 0; s < 2; ++s) {
            const int k0w = s * 8;
            uint32_t Afr[3][4];
            {
                const int arow = rowbase + (lane & 7) + ((lane >> 3) & 1) * 8;
                const int aoff = k0w + (lane >> 4) * 4;
#pragma unroll
                for (int comp = 0; comp < 3; ++comp)
                    ldsm4(Afr[comp], &xw[comp * XCOMP_W + arow * RSTR + aoff]);
            }
            const int brow = (lane >> 4) * 8 + (lane & 7);
            const int boff = k0w + ((lane >> 3) & 1) * 4;
#pragma unroll
            for (int p = 0; p < 4; ++p) {
                uint32_t Bfr[3][4];
#pragma unroll
                for (int comp = 0; comp < 3; ++comp)
                    ldsm4(Bfr[comp], &wcur[comp * WCOMP_W + (p * 16 + brow) * RSTR + boff]);
                const int pa[6] = {0, 0, 1, 0, 1, 2};
                const int pb[6] = {0, 1, 0, 2, 1, 0};
#pragma unroll
                for (int pr = 0; pr < 6; ++pr) {
                    mma_bf16(acc[2 * p],     Afr[pa[pr]], Bfr[pb[pr]][0], Bfr[pb[pr]][1]);
                    mma_bf16(acc[2 * p + 1], Afr[pa[pr]], Bfr[pb[pr]][2], Bfr[pb[pr]][3]);
                }
            }
        }
    }

    __syncthreads();                    // drain all MMA smem reads before aliasing

    // ---- logits to smem ----
#pragma unroll
    for (int n = 0; n < 8; ++n) {
        const int e = n * 8 + 2 * fk;
        *(float2*)&slog[(rowbase + fr) * SLW + e]     = make_float2(acc[n][0], acc[n][1]);
        *(float2*)&slog[(rowbase + 8 + fr) * SLW + e] = make_float2(acc[n][2], acc[n][3]);
    }
    __syncthreads();

    // ---- epilogue: 4 warps x 16 tokens ----
    const float NEG_INF = -CUDART_INF_F;
    const int mask32 = smask32;

    for (int tk = 0; tk < TMTOK / 4; ++tk) {
        const int tok = wid * (TMTOK / 4) + tk;
        const int gtok = tokBase + tok;
        if (gtok >= M) break;           // uniform within warp

        const float l0 = slog[tok * SLW + lane];
        const float l1 = slog[tok * SLW + lane + 32];
        float b0 = l0 + sbias[lane];
        float b1 = l1 + sbias[lane + 32];

        int   sel_idx = 0;
        float sel_logit = NEG_INF;

#pragma unroll
        for (int r = 0; r < KSEL; ++r) {
            float bv; int bi;
            if (b0 >= b1) { bv = b0; bi = lane; }       // tie -> lower index
            else          { bv = b1; bi = lane + 32; }
#pragma unroll
            for (int s = 16; s >= 1; s >>= 1) {
                const float ov = __shfl_xor_sync(0xffffffffu, bv, s);
                const int   oi = __shfl_xor_sync(0xffffffffu, bi, s);
                if (ov > bv || (ov == bv && oi < bi)) { bv = ov; bi = oi; }
            }
            if (lane == r) { sel_idx = bi; sel_logit = slog[tok * SLW + bi]; }
            if ((bi & 31) == lane) {                    // owner masks winner
                if (bi < 32) b0 = NEG_INF; else b1 = NEG_INF;
            }
        }

        const float lv = (lane < KSEL) ? sel_logit : NEG_INF;
        float mval = lv;
#pragma unroll
        for (int s = 16; s >= 1; s >>= 1)
            mval = fmaxf(mval, __shfl_xor_sync(0xffffffffu, mval, s));
        const float ev = (lane < KSEL) ? __expf(lv - mval) : 0.f;
        float ssum = ev;
#pragma unroll
        for (int s = 16; s >= 1; s >>= 1)
            ssum += __shfl_xor_sync(0xffffffffu, ssum, s);

        bool act;
        if (mask32) act = (((const unsigned int*)mask)[gtok] != 0u);
        else        act = (mask[gtok] != 0);

        if (lane < KSEL) {
            out_sel [(size_t)gtok * KSEL + lane] = (float)sel_idx;
            out_prob[(size_t)gtok * KSEL + lane] = ev / ssum;
            if (act) atomicAdd(&shist[sel_idx], 1);
        }
        if (lane == 0 && act) atomicAdd(&sactive, 1);
    }

    __syncthreads();
    if (tid < LEXP) g_hist_cta[blockIdx.x][tid] = shist[tid];
    if (tid == 0)   g_act_cta[blockIdx.x] = sactive;
    __syncthreads();

    // ---- last-CTA finalize (threadfence reduction pattern) ----
    if (tid == 0) {
        __threadfence();
        const int old = atomicAdd(&g_ticket, 1);
        sflag = (old == ncta - 1) ? 1 : 0;
    }
    __syncthreads();
    if (sflag) {
        __threadfence();
        const int l = tid & 63;
        const int g = tid >> 6;                 // 0..1
        int h = 0;
        for (int cc = g; cc < ncta; cc += 2) h += g_hist_cta[cc][l];
        spart[g][l] = h;
        int a = 0;
        for (int cc = tid; cc < ncta; cc += NTHREADS) a += g_act_cta[cc];
        if (a) atomicAdd(&sred, a);
        __syncthreads();
        if (tid == 0) {
            const float denom = (float)sred * (float)KSEL;
            const float invL = 1.f / (float)LEXP;
            float s = 0.f, mx = -CUDART_INF_F;
            for (int e = 0; e < LEXP; ++e) {
                const int hs = spart[0][e] + spart[1][e];
                const float d = (float)hs / denom - invL;
                s += d * d;
                mx = fmaxf(mx, d);
            }
            out_scal[0] = (float)LEXP * s;                // load_balance_loss
            if (has_vio) out_scal[1] = (float)LEXP * mx;  // max_vio
            g_ticket = 0;                                 // reset for next replay
        }
    }
}

extern "C" void kernel_launch(void* const* d_in, const int* in_sizes, int n_in,
                              void* d_out, int out_size) {
    const float* x    = (const float*)d_in[0];
    const float* Wr   = (const float*)d_in[1];
    const float* bias = (const float*)d_in[2];
    const unsigned char* mask = (const unsigned char*)d_in[3];

    const int L = in_sizes[2];          // 64
    const int H = in_sizes[1] / L;      // 2048
    const int M = in_sizes[0] / H;      // 16384 tokens (B*N)

    float* out = (float*)d_out;
    float* out_sel  = out;                          // (M, K) indices as float
    float* out_prob = out + (size_t)M * KSEL;       // (M, K) probs
    float* out_scal = out + (size_t)2 * M * KSEL;   // loss [, max_vio]
    const int has_vio = (out_size >= 2 * M * KSEL + 2) ? 1 : 0;

    const int grid = (M + TMTOK - 1) / TMTOK;       // 256 for M=16384
    wsplit_kernel<<<LEXP, 256>>>(Wr, H);
    router_kernel<<<grid, NTHREADS, DYN_BYTES>>>(x, Wr, bias, mask,
                                                 out_sel, out_prob, out_scal,
                                                 has_vio, M, H);
}

// round 16
// speedup vs baseline: 1.0690x; 1.0690x over previous
#include <cuda_runtime.h>
#include <math_constants.h>
#include <cstdint>

#define LEXP 64
#define KSEL 8
#define TMTOK 112        // tokens per CTA -> grid 147 = one full wave on 148 SMs
#define KC   32          // K floats per chunk (16 bf16x2 words per row)
#define NTHREADS 256
#define MAXCTAS 512
#define RSTR 20          // uint32 words per staged row -> conflict-free ldmatrix

#define XCOMP_B (TMTOK * RSTR * 4)       // 8960 per x component
#define WCOMP_B (LEXP * RSTR * 4)        // 5120 per w component
#define OFF_XA 0
#define OFF_XB XCOMP_B
#define OFF_XC (2 * XCOMP_B)
#define OFF_WD (3 * XCOMP_B)             // 26880
#define OFF_WE (OFF_WD + WCOMP_B)
#define OFF_WF (OFF_WE + WCOMP_B)
#define DYN_BYTES (OFF_WF + WCOMP_B)     // 42240 (< 48KB default)
#define SLW 66                            // slog row stride; 112*66*4 = 29568 fits

__device__ uint32_t g_wsplit[3][LEXP][1024];   // bf16x2 words, H=2048 -> 1024/row
__device__ int g_hist_cta[MAXCTAS][LEXP];
__device__ int g_act_cta[MAXCTAS];
__device__ int g_ticket;                       // zero-init; reset by last CTA

static __device__ __forceinline__ uint32_t cvt2(float hi, float lo) {
    uint32_t d;
    asm("cvt.rn.bf16x2.f32 %0, %1, %2;" : "=r"(d) : "f"(hi), "f"(lo));
    return d;
}
static __device__ __forceinline__ float lo_f(uint32_t p) { return __uint_as_float(p << 16); }
static __device__ __forceinline__ float hi_f(uint32_t p) { return __uint_as_float(p & 0xFFFF0000u); }

static __device__ __forceinline__ void split3(float f0, float f1,
                                              uint32_t& pa, uint32_t& pb, uint32_t& pc) {
    pa = cvt2(f1, f0);
    const float r0 = f0 - lo_f(pa), r1 = f1 - hi_f(pa);   // exact
    pb = cvt2(r1, r0);
    const float s0 = r0 - lo_f(pb), s1 = r1 - hi_f(pb);   // exact
    pc = cvt2(s1, s0);
}

static __device__ __forceinline__ void mma_bf16(float* d, const uint32_t* a,
                                                uint32_t b0, uint32_t b1) {
    asm volatile(
        "mma.sync.aligned.m16n8k16.row.col.f32.bf16.bf16.f32 "
        "{%0,%1,%2,%3}, {%4,%5,%6,%7}, {%8,%9}, {%0,%1,%2,%3};"
        : "+f"(d[0]), "+f"(d[1]), "+f"(d[2]), "+f"(d[3])
        : "r"(a[0]), "r"(a[1]), "r"(a[2]), "r"(a[3]), "r"(b0), "r"(b1));
}

static __device__ __forceinline__ void ldsm4(uint32_t* r, const void* p) {
    const uint32_t a = (uint32_t)__cvta_generic_to_shared(p);
    asm volatile("ldmatrix.sync.aligned.m8n8.x4.shared.b16 {%0,%1,%2,%3}, [%4];"
        : "=r"(r[0]), "=r"(r[1]), "=r"(r[2]), "=r"(r[3]) : "r"(a));
}

__global__ void wsplit_kernel(const float* __restrict__ Wr, int H) {
    const int e = blockIdx.x;           // 64 experts
    const int t = threadIdx.x;          // 256
    const int nw = H / 2;               // 1024 words
    for (int w = t; w < nw; w += 256) {
        const float f0 = Wr[(size_t)e * H + 2 * w];
        const float f1 = Wr[(size_t)e * H + 2 * w + 1];
        uint32_t a, b, c;
        split3(f0, f1, a, b, c);
        g_wsplit[0][e][w] = a;
        g_wsplit[1][e][w] = b;
        g_wsplit[2][e][w] = c;
    }
}

extern __shared__ char dyn_raw[];

__global__ void __launch_bounds__(NTHREADS, 1)
router_kernel(const float* __restrict__ x, const float* __restrict__ Wr,
              const float* __restrict__ bias, const unsigned char* __restrict__ mask,
              float* __restrict__ out_sel, float* __restrict__ out_prob,
              float* __restrict__ out_scal, int has_vio, int M, int H)
{
    uint32_t* xcomp[3] = { (uint32_t*)(dyn_raw + OFF_XA), (uint32_t*)(dyn_raw + OFF_XB),
                           (uint32_t*)(dyn_raw + OFF_XC) };
    uint32_t* wcomp[3] = { (uint32_t*)(dyn_raw + OFF_WD), (uint32_t*)(dyn_raw + OFF_WE),
                           (uint32_t*)(dyn_raw + OFF_WF) };
    float* slog = (float*)dyn_raw;      // alias, used after MMA drain

    __shared__ float sbias[LEXP];
    __shared__ int   shist[LEXP];
    __shared__ int   spart[4][LEXP];
    __shared__ int   sactive, smask32, sflag, sred;

    const int tid = threadIdx.x;
    const int wid = tid >> 5;
    const int lane = tid & 31;
    const int tokBase = blockIdx.x * TMTOK;
    const int ncta = gridDim.x;

    if (tid < LEXP) { sbias[tid] = bias[tid]; shist[tid] = 0; }
    if (tid == 0) {
        sactive = 0; sred = 0;
        const unsigned char b0 = mask[0];
        const unsigned char b1 = mask[1];
        smask32 = (b0 != 0 && b1 != 0) ? 0 : 1;
    }

    // MMA mapping: warps 0..6 own one 16-row mtile over the FULL K
    // (per-accumulator op order identical to validated R11/R14)
    const bool mma_warp = (wid < 7);
    const int rowbase = wid * 16;
    const int fr = lane >> 2;
    const int fk = lane & 3;

    float acc[8][4];                    // [ntile][frag]
#pragma unroll
    for (int n = 0; n < 8; ++n)
#pragma unroll
        for (int j = 0; j < 4; ++j) acc[n][j] = 0.f;

    // staging mapping
    const int srow = tid >> 3;          // 0..31
    const int sq = tid & 7;

    float4 xr[4];
    uint4  wv[3];
    const int nchunk = H / KC;

    // prologue: prefetch chunk 0
#pragma unroll
    for (int p = 0; p < 4; ++p) {
        const int row = p * 32 + srow;
        const int gtok = tokBase + row;
        xr[p] = (row < TMTOK && gtok < M)
              ? *(const float4*)(x + (size_t)gtok * H + sq * 4)
              : make_float4(0.f, 0.f, 0.f, 0.f);
    }
#pragma unroll
    for (int i = 0; i < 3; ++i) {
        const int idx = i * 256 + tid;          // 0..767
        const int rc = idx >> 2, q = idx & 3;
        wv[i] = *(const uint4*)&g_wsplit[rc >> 6][rc & 63][q * 4];
    }

    for (int c = 0; c < nchunk; ++c) {
        __syncthreads();                // previous chunk's MMA reads complete
        // ---- store staged chunk: x converted, w copied ----
#pragma unroll
        for (int p = 0; p < 4; ++p) {
            const int row = p * 32 + srow;
            if (row < TMTOK) {
                const int base = row * RSTR + sq * 2;
                uint32_t a0, b0, c0, a1, b1, c1;
                split3(xr[p].x, xr[p].y, a0, b0, c0);
                split3(xr[p].z, xr[p].w, a1, b1, c1);
                *(unsigned long long*)&xcomp[0][base] = (unsigned long long)a0 | ((unsigned long long)a1 << 32);
                *(unsigned long long*)&xcomp[1][base] = (unsigned long long)b0 | ((unsigned long long)b1 << 32);
                *(unsigned long long*)&xcomp[2][base] = (unsigned long long)c0 | ((unsigned long long)c1 << 32);
            }
        }
#pragma unroll
        for (int i = 0; i < 3; ++i) {
            const int idx = i * 256 + tid;
            const int rc = idx >> 2, q = idx & 3;
            *(uint4*)&wcomp[rc >> 6][(rc & 63) * RSTR + q * 4] = wv[i];
        }
        __syncthreads();

        // ---- prefetch next chunk (hidden under MMA) ----
        if (c + 1 < nchunk) {
            const int kb = (c + 1) * KC;
#pragma unroll
            for (int p = 0; p < 4; ++p) {
                const int row = p * 32 + srow;
                const int gtok = tokBase + row;
                xr[p] = (row < TMTOK && gtok < M)
                      ? *(const float4*)(x + (size_t)gtok * H + kb + sq * 4)
                      : make_float4(0.f, 0.f, 0.f, 0.f);
            }
            const int kw = (c + 1) * (KC / 2);
#pragma unroll
            for (int i = 0; i < 3; ++i) {
                const int idx = i * 256 + tid;
                const int rc = idx >> 2, q = idx & 3;
                wv[i] = *(const uint4*)&g_wsplit[rc >> 6][rc & 63][kw + q * 4];
            }
        }

        // ---- MMA: 2 ksteps; per kstep load ALL fragments then issue
        //      pr-outer / p-inner -> 8 independent accumulator chains.
        //      Per-accumulator product order: ad,ae,bd,af,be,cd (R11) ----
        if (mma_warp) {
#pragma unroll
            for (int s = 0; s < 2; ++s) {
                const int k0w = s * 8;
                uint32_t Afr[3][4];
                {
                    const int arow = rowbase + (lane & 7) + ((lane >> 3) & 1) * 8;
                    const int aoff = k0w + (lane >> 4) * 4;
#pragma unroll
                    for (int comp = 0; comp < 3; ++comp)
                        ldsm4(Afr[comp], &xcomp[comp][arow * RSTR + aoff]);
                }
                uint32_t Ball[4][3][4];
                {
                    const int brow = (lane >> 4) * 8 + (lane & 7);
                    const int boff = k0w + ((lane >> 3) & 1) * 4;
#pragma unroll
                    for (int p = 0; p < 4; ++p)
#pragma unroll
                        for (int comp = 0; comp < 3; ++comp)
                            ldsm4(Ball[p][comp], &wcomp[comp][(p * 16 + brow) * RSTR + boff]);
                }
                const int pa[6] = {0, 0, 1, 0, 1, 2};
                const int pb[6] = {0, 1, 0, 2, 1, 0};
#pragma unroll
                for (int pr = 0; pr < 6; ++pr)
#pragma unroll
                    for (int p = 0; p < 4; ++p) {
                        mma_bf16(acc[2 * p],     Afr[pa[pr]], Ball[p][pb[pr]][0], Ball[p][pb[pr]][1]);
                        mma_bf16(acc[2 * p + 1], Afr[pa[pr]], Ball[p][pb[pr]][2], Ball[p][pb[pr]][3]);
                    }
            }
        }
    }

    __syncthreads();                    // drain all MMA smem reads before aliasing

    // ---- logits to smem ----
    if (mma_warp) {
#pragma unroll
        for (int n = 0; n < 8; ++n) {
            const int e = n * 8 + 2 * fk;
            *(float2*)&slog[(rowbase + fr) * SLW + e]     = make_float2(acc[n][0], acc[n][1]);
            *(float2*)&slog[(rowbase + 8 + fr) * SLW + e] = make_float2(acc[n][2], acc[n][3]);
        }
    }
    __syncthreads();

    // ---- epilogue: 8 warps x 14 tokens ----
    const float NEG_INF = -CUDART_INF_F;
    const int mask32 = smask32;

    for (int tk = 0; tk < TMTOK / 8; ++tk) {
        const int tok = wid * (TMTOK / 8) + tk;
        const int gtok = tokBase + tok;
        if (gtok >= M) break;           // uniform within warp

        const float l0 = slog[tok * SLW + lane];
        const float l1 = slog[tok * SLW + lane + 32];
        float b0 = l0 + sbias[lane];
        float b1 = l1 + sbias[lane + 32];

        int   sel_idx = 0;
        float sel_logit = NEG_INF;

#pragma unroll
        for (int r = 0; r < KSEL; ++r) {
            float bv; int bi;
            if (b0 >= b1) { bv = b0; bi = lane; }       // tie -> lower index
            else          { bv = b1; bi = lane + 32; }
#pragma unroll
            for (int s = 16; s >= 1; s >>= 1) {
                const float ov = __shfl_xor_sync(0xffffffffu, bv, s);
                const int   oi = __shfl_xor_sync(0xffffffffu, bi, s);
                if (ov > bv || (ov == bv && oi < bi)) { bv = ov; bi = oi; }
            }
            if (lane == r) { sel_idx = bi; sel_logit = slog[tok * SLW + bi]; }
            if ((bi & 31) == lane) {                    // owner masks winner
                if (bi < 32) b0 = NEG_INF; else b1 = NEG_INF;
            }
        }

        const float lv = (lane < KSEL) ? sel_logit : NEG_INF;
        float mval = lv;
#pragma unroll
        for (int s = 16; s >= 1; s >>= 1)
            mval = fmaxf(mval, __shfl_xor_sync(0xffffffffu, mval, s));
        const float ev = (lane < KSEL) ? __expf(lv - mval) : 0.f;
        float ssum = ev;
#pragma unroll
        for (int s = 16; s >= 1; s >>= 1)
            ssum += __shfl_xor_sync(0xffffffffu, ssum, s);

        bool act;
        if (mask32) act = (((const unsigned int*)mask)[gtok] != 0u);
        else        act = (mask[gtok] != 0);

        if (lane < KSEL) {
            out_sel [(size_t)gtok * KSEL + lane] = (float)sel_idx;
            out_prob[(size_t)gtok * KSEL + lane] = ev / ssum;
            if (act) atomicAdd(&shist[sel_idx], 1);
        }
        if (lane == 0 && act) atomicAdd(&sactive, 1);
    }

    __syncthreads();
    if (tid < LEXP) g_hist_cta[blockIdx.x][tid] = shist[tid];
    if (tid == 0)   g_act_cta[blockIdx.x] = sactive;
    __syncthreads();

    // ---- last-CTA finalize (threadfence reduction pattern) ----
    if (tid == 0) {
        __threadfence();
        const int old = atomicAdd(&g_ticket, 1);
        sflag = (old == ncta - 1) ? 1 : 0;
    }
    __syncthreads();
    if (sflag) {
        __threadfence();
        const int l = tid & 63;
        const int g = tid >> 6;                 // 0..3
        int h = 0;
        for (int cc = g; cc < ncta; cc += 4) h += g_hist_cta[cc][l];
        spart[g][l] = h;
        if (tid < ncta) atomicAdd(&sred, g_act_cta[tid]);
        __syncthreads();
        if (tid == 0) {
            const float denom = (float)sred * (float)KSEL;
            const float invL = 1.f / (float)LEXP;
            float s = 0.f, mx = -CUDART_INF_F;
            for (int e = 0; e < LEXP; ++e) {
                const int hs = spart[0][e] + spart[1][e] + spart[2][e] + spart[3][e];
                const float d = (float)hs / denom - invL;
                s += d * d;
                mx = fmaxf(mx, d);
            }
            out_scal[0] = (float)LEXP * s;                // load_balance_loss
            if (has_vio) out_scal[1] = (float)LEXP * mx;  // max_vio
            g_ticket = 0;                                 // reset for next replay
        }
    }
}

extern "C" void kernel_launch(void* const* d_in, const int* in_sizes, int n_in,
                              void* d_out, int out_size) {
    const float* x    = (const float*)d_in[0];
    const float* Wr   = (const float*)d_in[1];
    const float* bias = (const float*)d_in[2];
    const unsigned char* mask = (const unsigned char*)d_in[3];

    const int L = in_sizes[2];          // 64
    const int H = in_sizes[1] / L;      // 2048
    const int M = in_sizes[0] / H;      // 16384 tokens (B*N)

    float* out = (float*)d_out;
    float* out_sel  = out;                          // (M, K) indices as float
    float* out_prob = out + (size_t)M * KSEL;       // (M, K) probs
    float* out_scal = out + (size_t)2 * M * KSEL;   // loss [, max_vio]
    const int has_vio = (out_size >= 2 * M * KSEL + 2) ? 1 : 0;

    const int grid = (M + TMTOK - 1) / TMTOK;       // 147 for M=16384
    wsplit_kernel<<<LEXP, 256>>>(Wr, H);
    router_kernel<<<grid, NTHREADS, DYN_BYTES>>>(x, Wr, bias, mask,
                                                 out_sel, out_prob, out_scal,
                                                 has_vio, M, H);
}